// round 16
// baseline (speedup 1.0000x reference)
#include <cuda_runtime.h>
#include <math.h>
#include <stdint.h>

#define SQn   2048
#define SKn   64
#define Cn    256
#define HWn   256
#define En    512
#define NPn   (SQn*SKn)
#define NHn   8
#define HDn   64

typedef unsigned long long u64;
typedef ulonglong2 ull2;

__device__ __forceinline__ u64 fma2(u64 a, u64 b, u64 c) {
    u64 d;
    asm("fma.rn.f32x2 %0, %1, %2, %3;" : "=l"(d) : "l"(a), "l"(b), "l"(c));
    return d;
}
__device__ __forceinline__ u64 pack2(float lo, float hi) {
    u64 v;
    asm("mov.b64 %0, {%1, %2};" : "=l"(v) : "f"(lo), "f"(hi));
    return v;
}
__device__ __forceinline__ float2 unpack2(u64 v) {
    float lo, hi;
    asm("mov.b64 {%0, %1}, %2;" : "=f"(lo), "=f"(hi) : "l"(v));
    return make_float2(lo, hi);
}
__device__ __forceinline__ u64 splat2(float a) { return pack2(a, a); }

// ---------------- scratch ----------------
__device__ float g_Zt[(size_t)Cn*HWn*HWn];
__device__ float g_key2[(size_t)NPn*256];
__device__ float g_ql[(size_t)SQn*En];
__device__ float g_qk[(size_t)SQn*NHn*En];
__device__ float g_ctx[(size_t)SQn*NHn*En];
__device__ float g_out1[(size_t)SQn*En];

// ---------------- 1) transpose Z (C, HW*HW) -> Zt (HW*HW, C) ----------------
__global__ void transpose_kernel(const float* __restrict__ Z) {
    __shared__ float tile[32][33];
    int xy0 = blockIdx.x * 32;
    int c0  = blockIdx.y * 32;
    int tx = threadIdx.x, ty = threadIdx.y;   // 32 x 8
    #pragma unroll
    for (int i = 0; i < 32; i += 8)
        tile[ty + i][tx] = Z[(long)(c0 + ty + i) * (HWn*HWn) + xy0 + tx];
    __syncthreads();
    #pragma unroll
    for (int i = 0; i < 32; i += 8)
        g_Zt[(long)(xy0 + ty + i) * Cn + c0 + tx] = tile[tx][ty + i];
}

// ============ proven 128x64 f32x2 GEMM body (R8) ============
// C[m][n] = sum_k A[m*lda+k] * B[n*ldbn + k*ldbk] + bias[n]
__device__ __forceinline__ void gemm128_body(
    float* As, float* Bs, int t,
    const float* __restrict__ A, int lda,
    const float* __restrict__ B, int ldbn, int ldbk,
    float* __restrict__ Cp, int ldc, const float* __restrict__ bias,
    int m0, int n0, int K)
{
    int tx = t & 15, ty = t >> 4;
    int ar = t >> 2, ac = (t & 3) * 4;
    const bool bvec = (ldbk == 1);
    const float* Abase = A + (long)(m0 + ar) * lda + ac;

    float4 ra0 = *(const float4*)(Abase);
    float4 ra1 = *(const float4*)(Abase + (long)64 * lda);
    float4 rb; float rbs[4];
    if (bvec) {
        rb = *(const float4*)(B + (long)(n0 + ar) * ldbn + ac);
    } else {
        #pragma unroll
        for (int q = 0; q < 4; q++) {
            int idx = t + 256*q; int nn = idx & 63, kk = idx >> 6;
            rbs[q] = B[(long)(n0 + nn) + (long)kk * ldbk];
        }
    }

    u64 acc2[4][4] = {};
    for (int k0 = 0; k0 < K; k0 += 16) {
        As[(ac+0)*132+ar]=ra0.x; As[(ac+1)*132+ar]=ra0.y; As[(ac+2)*132+ar]=ra0.z; As[(ac+3)*132+ar]=ra0.w;
        As[(ac+0)*132+ar+64]=ra1.x; As[(ac+1)*132+ar+64]=ra1.y; As[(ac+2)*132+ar+64]=ra1.z; As[(ac+3)*132+ar+64]=ra1.w;
        if (bvec) {
            Bs[(ac+0)*68+ar]=rb.x; Bs[(ac+1)*68+ar]=rb.y; Bs[(ac+2)*68+ar]=rb.z; Bs[(ac+3)*68+ar]=rb.w;
        } else {
            #pragma unroll
            for (int q = 0; q < 4; q++) {
                int idx = t + 256*q; int nn = idx & 63, kk = idx >> 6;
                Bs[kk*68+nn] = rbs[q];
            }
        }
        __syncthreads();
        if (k0 + 16 < K) {
            const float* An = Abase + k0 + 16;
            ra0 = *(const float4*)(An);
            ra1 = *(const float4*)(An + (long)64 * lda);
            if (bvec) {
                rb = *(const float4*)(B + (long)(n0 + ar) * ldbn + k0 + 16 + ac);
            } else {
                #pragma unroll
                for (int q = 0; q < 4; q++) {
                    int idx = t + 256*q; int nn = idx & 63, kk = idx >> 6;
                    rbs[q] = B[(long)(n0 + nn) + (long)(k0 + 16 + kk) * ldbk];
                }
            }
        }
        #pragma unroll
        for (int k = 0; k < 16; k++) {
            ull2 aA = *(const ull2*)(&As[k*132 + ty*8]);
            ull2 aB = *(const ull2*)(&As[k*132 + ty*8 + 4]);
            float4 bq = *(const float4*)(&Bs[k*68 + tx*4]);
            u64 bs0=splat2(bq.x), bs1=splat2(bq.y), bs2=splat2(bq.z), bs3=splat2(bq.w);
            acc2[0][0]=fma2(aA.x,bs0,acc2[0][0]); acc2[0][1]=fma2(aA.x,bs1,acc2[0][1]);
            acc2[0][2]=fma2(aA.x,bs2,acc2[0][2]); acc2[0][3]=fma2(aA.x,bs3,acc2[0][3]);
            acc2[1][0]=fma2(aA.y,bs0,acc2[1][0]); acc2[1][1]=fma2(aA.y,bs1,acc2[1][1]);
            acc2[1][2]=fma2(aA.y,bs2,acc2[1][2]); acc2[1][3]=fma2(aA.y,bs3,acc2[1][3]);
            acc2[2][0]=fma2(aB.x,bs0,acc2[2][0]); acc2[2][1]=fma2(aB.x,bs1,acc2[2][1]);
            acc2[2][2]=fma2(aB.x,bs2,acc2[2][2]); acc2[2][3]=fma2(aB.x,bs3,acc2[2][3]);
            acc2[3][0]=fma2(aB.y,bs0,acc2[3][0]); acc2[3][1]=fma2(aB.y,bs1,acc2[3][1]);
            acc2[3][2]=fma2(aB.y,bs2,acc2[3][2]); acc2[3][3]=fma2(aB.y,bs3,acc2[3][3]);
        }
        __syncthreads();
    }
    float4 bb = make_float4(0.f,0.f,0.f,0.f);
    if (bias) bb = *(const float4*)(bias + n0 + tx*4);
    #pragma unroll
    for (int mp = 0; mp < 4; mp++) {
        float2 u0=unpack2(acc2[mp][0]), u1=unpack2(acc2[mp][1]);
        float2 u2=unpack2(acc2[mp][2]), u3=unpack2(acc2[mp][3]);
        int mA = m0 + ty*8 + mp*2, mB = mA + 1;
        *(float4*)(&Cp[(long)mA*ldc + n0 + tx*4]) =
            make_float4(u0.x+bb.x, u1.x+bb.y, u2.x+bb.z, u3.x+bb.w);
        *(float4*)(&Cp[(long)mB*ldc + n0 + tx*4]) =
            make_float4(u0.y+bb.x, u1.y+bb.y, u2.y+bb.z, u3.y+bb.w);
    }
}

// ---------------- 2) FAT kernel (R8): gemm1(query fused) | qz->out copy | interp ----------------
#define FAT_GEMM_BLKS 128
#define FAT_COPY_BLKS 16
#define FAT_INTERP_OFF (FAT_GEMM_BLKS + FAT_COPY_BLKS)

struct InterpS { float sres[256][33]; int soff[32]; float sdx[32], sdy[32]; };
struct GemmS   { float As[16][132]; float Bs[16][68]; };

__global__ __launch_bounds__(256)
void fat_kernel(const float* __restrict__ r,
                const float* __restrict__ q_z,
                const float* __restrict__ Q,
                const float* __restrict__ w2,
                const float* __restrict__ b2,
                const float* __restrict__ in_proj_w,
                const float* __restrict__ in_proj_b,
                float* __restrict__ outp) {
    __shared__ __align__(16) char smraw[sizeof(InterpS)];
    int bx = blockIdx.x;
    int t = threadIdx.x;

    if (bx < FAT_GEMM_BLKS) {
        GemmS* S = (GemmS*)smraw;
        int tx = t & 15, ty = t >> 4;
        int m0 = (bx >> 3) * 128;
        int n0 = (bx & 7) * 64;
        int ar = t >> 2, ac = (t & 3) * 4;

        int rowA = m0 + ar, rowB = m0 + ar + 64;
        float qa0 = Q[rowA*3+0], qa1 = Q[rowA*3+1], qa2 = Q[rowA*3+2];
        float qb0 = Q[rowB*3+0], qb1 = Q[rowB*3+1], qb2 = Q[rowB*3+2];

        auto loadA = [&](int row, float q0, float q1, float q2, int k)->float4 {
            if (k < 256) {
                return *(const float4*)(q_z + (long)row*256 + k);
            } else {
                int h = k - 256;
                const float* w2r = w2 + h*3;
                float4 v;
                v.x = q0*w2r[0] + q1*w2r[1]  + q2*w2r[2]  + b2[h+0];
                v.y = q0*w2r[3] + q1*w2r[4]  + q2*w2r[5]  + b2[h+1];
                v.z = q0*w2r[6] + q1*w2r[7]  + q2*w2r[8]  + b2[h+2];
                v.w = q0*w2r[9] + q1*w2r[10] + q2*w2r[11] + b2[h+3];
                return v;
            }
        };

        float4 ra0 = loadA(rowA, qa0, qa1, qa2, ac);
        float4 ra1 = loadA(rowB, qb0, qb1, qb2, ac);
        float4 rb  = *(const float4*)(in_proj_w + (long)(n0 + ar) * En + ac);

        u64 acc2[4][4] = {};
        for (int k0 = 0; k0 < En; k0 += 16) {
            S->As[ac+0][ar]    = ra0.x; S->As[ac+1][ar]    = ra0.y; S->As[ac+2][ar]    = ra0.z; S->As[ac+3][ar]    = ra0.w;
            S->As[ac+0][ar+64] = ra1.x; S->As[ac+1][ar+64] = ra1.y; S->As[ac+2][ar+64] = ra1.z; S->As[ac+3][ar+64] = ra1.w;
            S->Bs[ac+0][ar] = rb.x; S->Bs[ac+1][ar] = rb.y; S->Bs[ac+2][ar] = rb.z; S->Bs[ac+3][ar] = rb.w;
            __syncthreads();
            if (k0 + 16 < En) {
                ra0 = loadA(rowA, qa0, qa1, qa2, k0 + 16 + ac);
                ra1 = loadA(rowB, qb0, qb1, qb2, k0 + 16 + ac);
                rb  = *(const float4*)(in_proj_w + (long)(n0 + ar) * En + k0 + 16 + ac);
            }
            #pragma unroll
            for (int k = 0; k < 16; k++) {
                ull2 aA = *(const ull2*)(&S->As[k][ty*8]);
                ull2 aB = *(const ull2*)(&S->As[k][ty*8+4]);
                float4 bq = *(const float4*)(&S->Bs[k][tx*4]);
                u64 ap0 = aA.x, ap1 = aA.y, ap2 = aB.x, ap3 = aB.y;
                u64 bs0 = splat2(bq.x), bs1 = splat2(bq.y), bs2 = splat2(bq.z), bs3 = splat2(bq.w);
                acc2[0][0]=fma2(ap0,bs0,acc2[0][0]); acc2[0][1]=fma2(ap0,bs1,acc2[0][1]);
                acc2[0][2]=fma2(ap0,bs2,acc2[0][2]); acc2[0][3]=fma2(ap0,bs3,acc2[0][3]);
                acc2[1][0]=fma2(ap1,bs0,acc2[1][0]); acc2[1][1]=fma2(ap1,bs1,acc2[1][1]);
                acc2[1][2]=fma2(ap1,bs2,acc2[1][2]); acc2[1][3]=fma2(ap1,bs3,acc2[1][3]);
                acc2[2][0]=fma2(ap2,bs0,acc2[2][0]); acc2[2][1]=fma2(ap2,bs1,acc2[2][1]);
                acc2[2][2]=fma2(ap2,bs2,acc2[2][2]); acc2[2][3]=fma2(ap2,bs3,acc2[2][3]);
                acc2[3][0]=fma2(ap3,bs0,acc2[3][0]); acc2[3][1]=fma2(ap3,bs1,acc2[3][1]);
                acc2[3][2]=fma2(ap3,bs2,acc2[3][2]); acc2[3][3]=fma2(ap3,bs3,acc2[3][3]);
            }
            __syncthreads();
        }
        float4 bb = *(const float4*)(in_proj_b + n0 + tx*4);
        #pragma unroll
        for (int mp = 0; mp < 4; mp++) {
            float2 u0 = unpack2(acc2[mp][0]);
            float2 u1 = unpack2(acc2[mp][1]);
            float2 u2 = unpack2(acc2[mp][2]);
            float2 u3 = unpack2(acc2[mp][3]);
            int mA = m0 + ty*8 + mp*2, mB = mA + 1;
            *(float4*)(&g_ql[(long)mA * En + n0 + tx*4]) =
                make_float4(u0.x+bb.x, u1.x+bb.y, u2.x+bb.z, u3.x+bb.w);
            *(float4*)(&g_ql[(long)mB * En + n0 + tx*4]) =
                make_float4(u0.y+bb.x, u1.y+bb.y, u2.y+bb.z, u3.y+bb.w);
        }
    } else if (bx < FAT_INTERP_OFF) {
        int r0 = (bx - FAT_GEMM_BLKS) * 128;
        #pragma unroll
        for (int i = 0; i < 32; i++) {
            int idx = i * 256 + t;
            int row = r0 + (idx >> 6);
            int c4  = (idx & 63) * 4;
            float4 v = *(const float4*)(q_z + (long)row*256 + c4);
            *(float4*)(outp + (long)row*768 + c4) = v;
        }
    } else {
        InterpS* S = (InterpS*)smraw;
        int p0 = (bx - FAT_INTERP_OFF) * 32;
        if (t < 32) {
            float x = r[2*(p0+t)], y = r[2*(p0+t)+1];
            int x1 = (int)x, y1 = (int)y;
            S->soff[t] = (x1*HWn + y1)*Cn;
            S->sdx[t] = x - (float)x1;
            S->sdy[t] = y - (float)y1;
        }
        __syncthreads();
        int wp = t >> 5, l = t & 31;
        #pragma unroll
        for (int pi = 0; pi < 4; pi++) {
            int pl = wp*4 + pi;
            long off = S->soff[pl];
            float dx = S->sdx[pl], dy = S->sdy[pl];
            float omdx = 1.0f - dx, omdy = 1.0f - dy;
            #pragma unroll
            for (int rep = 0; rep < 2; rep++) {
                int c = rep*128 + l*4;
                const float* z11 = g_Zt + off + c;
                float4 a  = *(const float4*)(z11);
                float4 cq = *(const float4*)(z11 + Cn);
                float4 b  = *(const float4*)(z11 + HWn*Cn);
                float4 d  = *(const float4*)(z11 + HWn*Cn + Cn);
                S->sres[c+0][pl] = (a.x*omdx + b.x*dx)*omdy + (cq.x*omdx + d.x*dx)*dy;
                S->sres[c+1][pl] = (a.y*omdx + b.y*dx)*omdy + (cq.y*omdx + d.y*dx)*dy;
                S->sres[c+2][pl] = (a.z*omdx + b.z*dx)*omdy + (cq.z*omdx + d.z*dx)*dy;
                S->sres[c+3][pl] = (a.w*omdx + b.w*dx)*omdy + (cq.w*omdx + d.w*dx)*dy;
            }
        }
        __syncthreads();
        long rowhi = (long)(p0 >> 8);
        int  colb  = p0 & 255;
        #pragma unroll
        for (int i = 0; i < 32; i++) {
            int c = wp*32 + i;
            g_key2[((long)c*512 + rowhi)*256 + colb + l] = S->sres[c][l];
        }
    }
}

// ---------------- 3) qk gemm (standalone, proven) ----------------
__global__ __launch_bounds__(256)
void qk_kernel(const float* __restrict__ in_proj_w) {
    __shared__ float sm[16*132 + 16*68];
    int h = blockIdx.z;
    gemm128_body(sm, sm + 16*132, threadIdx.x,
                 g_ql + (long)h*HDn, En,
                 in_proj_w + (long)En*En + (long)h*HDn*En, 1, En,
                 g_qk + (long)h*En, NHn*En, (const float*)0,
                 blockIdx.y*128, blockIdx.x*64, HDn);
}

// ---------------- generic GEMM kernel (128x64, batched) for v / out ----------------
__global__ __launch_bounds__(256)
void gemm_kernel(const float* __restrict__ A, int lda, long sA,
                 const float* __restrict__ B, int ldbn, int ldbk, long sB,
                 float* __restrict__ Cp, int ldc, long sC,
                 const float* __restrict__ bias, long sBias, int K) {
    __shared__ float sm[16*132 + 16*68];
    int b = blockIdx.z;
    gemm128_body(sm, sm + 16*132, threadIdx.x,
                 A + (long)b*sA, lda,
                 B + (long)b*sB, ldbn, ldbk,
                 Cp + (long)b*sC, ldc,
                 bias ? bias + (long)b*sBias : (const float*)0,
                 blockIdx.y*128, blockIdx.x*64, K);
}

// ---------------- 4) fused attention v2: half-width skey, occ 3 ----------------
#define SKH 132
#define SQS 516
#define OFF_SQ   8448              /* skey 64*132 */
#define OFF_RED  12576             /* sq 8*516 */
#define OFF_SC   14624             /* red 4*512 */
#define OFF_SA   15136
#define OFF_SMAX 15648
#define OFF_SRS  15656
#define OFF_RXY  15664
#define OFF_W1E  15792
#define OFF_W1O  16048
#define OFF_B1S  16304
#define ATTN_FLTS 16560
#define ATTN_SMEM (ATTN_FLTS*4)

__global__ __launch_bounds__(256, 3)
void attn_kernel(const float* __restrict__ r, const float* __restrict__ w1,
                 const float* __restrict__ b1) {
    extern __shared__ float smf[];
    float* skey = smf;
    float* sq   = smf + OFF_SQ;
    float* red  = smf + OFF_RED;
    float* sc   = smf + OFF_SC;
    float* sa   = smf + OFF_SA;
    float* smax = smf + OFF_SMAX;
    float* srs  = smf + OFF_SRS;
    float* rxy  = smf + OFF_RXY;
    float* w1e  = smf + OFF_W1E;
    float* w1o  = smf + OFF_W1O;
    float* b1s  = smf + OFF_B1S;

    int b = blockIdx.x, t = threadIdx.x;
    const float* keyb = g_key2 + (long)b * (64*256);

    // ---- initial loads: skey half A (cols 0..127), sq, rxy, w1 staging ----
    #pragma unroll
    for (int q = 0; q < 8; q++) {
        int idx = t + 256*q;                 // 2048 float4
        int row = idx >> 5, c4 = (idx & 31) * 4;
        *(float4*)(skey + row*SKH + c4) = *(const float4*)(keyb + row*256 + c4);
    }
    {
        const float4* qsrc = (const float4*)(g_qk + (long)b * 4096);
        #pragma unroll
        for (int q = 0; q < 4; q++) {
            int idx = t + 256*q;
            int row = idx >> 7, c = idx & 127;
            *(float4*)(sq + row*SQS + c*4) = qsrc[row*128 + c];
        }
    }
    if (t < 128) rxy[t] = r[b*128 + t];
    w1e[t] = w1[2*t]; w1o[t] = w1[2*t+1]; b1s[t] = b1[t];
    __syncthreads();

    // ---- phase 1: 4 slices x 64 threads; micro 4h x 2k ----
    int s  = t >> 6;
    int t6 = t & 63;
    int hq = t6 >> 5;        // 0..1
    int kq = t6 & 31;        // k = kq, kq+32
    int h0 = hq * 4;
    u64 acc[4][2] = {};

    // pass A: global j = s*32 + st*4  (cols 0..127, skey local = global)
    {
        int jb = s * 32;
        #pragma unroll
        for (int st = 0; st < 8; st++) {
            int jj = jb + st*4;
            ull2 a0 = *(const ull2*)(sq + (h0+0)*SQS + jj);
            ull2 a1 = *(const ull2*)(sq + (h0+1)*SQS + jj);
            ull2 a2 = *(const ull2*)(sq + (h0+2)*SQS + jj);
            ull2 a3 = *(const ull2*)(sq + (h0+3)*SQS + jj);
            ull2 b0 = *(const ull2*)(skey + kq*SKH + jj);
            ull2 b1v= *(const ull2*)(skey + (kq+32)*SKH + jj);
            acc[0][0]=fma2(a0.x,b0.x,acc[0][0]);  acc[0][0]=fma2(a0.y,b0.y,acc[0][0]);
            acc[1][0]=fma2(a1.x,b0.x,acc[1][0]);  acc[1][0]=fma2(a1.y,b0.y,acc[1][0]);
            acc[2][0]=fma2(a2.x,b0.x,acc[2][0]);  acc[2][0]=fma2(a2.y,b0.y,acc[2][0]);
            acc[3][0]=fma2(a3.x,b0.x,acc[3][0]);  acc[3][0]=fma2(a3.y,b0.y,acc[3][0]);
            acc[0][1]=fma2(a0.x,b1v.x,acc[0][1]); acc[0][1]=fma2(a0.y,b1v.y,acc[0][1]);
            acc[1][1]=fma2(a1.x,b1v.x,acc[1][1]); acc[1][1]=fma2(a1.y,b1v.y,acc[1][1]);
            acc[2][1]=fma2(a2.x,b1v.x,acc[2][1]); acc[2][1]=fma2(a2.y,b1v.y,acc[2][1]);
            acc[3][1]=fma2(a3.x,b1v.x,acc[3][1]); acc[3][1]=fma2(a3.y,b1v.y,acc[3][1]);
        }
    }
    __syncthreads();
    // load skey half B (cols 128..255)
    #pragma unroll
    for (int q = 0; q < 8; q++) {
        int idx = t + 256*q;
        int row = idx >> 5, c4 = (idx & 31) * 4;
        *(float4*)(skey + row*SKH + c4) = *(const float4*)(keyb + row*256 + 128 + c4);
    }
    __syncthreads();
    // pass B: global j = 128 + local jj
    {
        int jb = s * 32;
        #pragma unroll
        for (int st = 0; st < 8; st++) {
            int jj = jb + st*4;
            ull2 a0 = *(const ull2*)(sq + (h0+0)*SQS + 128 + jj);
            ull2 a1 = *(const ull2*)(sq + (h0+1)*SQS + 128 + jj);
            ull2 a2 = *(const ull2*)(sq + (h0+2)*SQS + 128 + jj);
            ull2 a3 = *(const ull2*)(sq + (h0+3)*SQS + 128 + jj);
            ull2 b0 = *(const ull2*)(skey + kq*SKH + jj);
            ull2 b1v= *(const ull2*)(skey + (kq+32)*SKH + jj);
            acc[0][0]=fma2(a0.x,b0.x,acc[0][0]);  acc[0][0]=fma2(a0.y,b0.y,acc[0][0]);
            acc[1][0]=fma2(a1.x,b0.x,acc[1][0]);  acc[1][0]=fma2(a1.y,b0.y,acc[1][0]);
            acc[2][0]=fma2(a2.x,b0.x,acc[2][0]);  acc[2][0]=fma2(a2.y,b0.y,acc[2][0]);
            acc[3][0]=fma2(a3.x,b0.x,acc[3][0]);  acc[3][0]=fma2(a3.y,b0.y,acc[3][0]);
            acc[0][1]=fma2(a0.x,b1v.x,acc[0][1]); acc[0][1]=fma2(a0.y,b1v.y,acc[0][1]);
            acc[1][1]=fma2(a1.x,b1v.x,acc[1][1]); acc[1][1]=fma2(a1.y,b1v.y,acc[1][1]);
            acc[2][1]=fma2(a2.x,b1v.x,acc[2][1]); acc[2][1]=fma2(a2.y,b1v.y,acc[2][1]);
            acc[3][1]=fma2(a3.x,b1v.x,acc[3][1]); acc[3][1]=fma2(a3.y,b1v.y,acc[3][1]);
        }
    }
    // pass C: rproj, global j = 256 + s*64 + st*4
    {
        u64 xs0 = splat2(rxy[2*kq]),      ys0 = splat2(rxy[2*kq+1]);
        u64 xs1 = splat2(rxy[2*(kq+32)]), ys1 = splat2(rxy[2*(kq+32)+1]);
        #pragma unroll
        for (int st = 0; st < 16; st++) {
            int w = s*64 + st*4;
            int jj = 256 + w;
            ull2 a0 = *(const ull2*)(sq + (h0+0)*SQS + jj);
            ull2 a1 = *(const ull2*)(sq + (h0+1)*SQS + jj);
            ull2 a2 = *(const ull2*)(sq + (h0+2)*SQS + jj);
            ull2 a3 = *(const ull2*)(sq + (h0+3)*SQS + jj);
            ull2 we2 = *(const ull2*)(w1e + w);
            ull2 wo2 = *(const ull2*)(w1o + w);
            ull2 bc2 = *(const ull2*)(b1s + w);
            u64 p0x = fma2(xs0, we2.x, fma2(ys0, wo2.x, bc2.x));
            u64 p0y = fma2(xs0, we2.y, fma2(ys0, wo2.y, bc2.y));
            u64 p1x = fma2(xs1, we2.x, fma2(ys1, wo2.x, bc2.x));
            u64 p1y = fma2(xs1, we2.y, fma2(ys1, wo2.y, bc2.y));
            acc[0][0]=fma2(a0.x,p0x,acc[0][0]); acc[0][0]=fma2(a0.y,p0y,acc[0][0]);
            acc[1][0]=fma2(a1.x,p0x,acc[1][0]); acc[1][0]=fma2(a1.y,p0y,acc[1][0]);
            acc[2][0]=fma2(a2.x,p0x,acc[2][0]); acc[2][0]=fma2(a2.y,p0y,acc[2][0]);
            acc[3][0]=fma2(a3.x,p0x,acc[3][0]); acc[3][0]=fma2(a3.y,p0y,acc[3][0]);
            acc[0][1]=fma2(a0.x,p1x,acc[0][1]); acc[0][1]=fma2(a0.y,p1y,acc[0][1]);
            acc[1][1]=fma2(a1.x,p1x,acc[1][1]); acc[1][1]=fma2(a1.y,p1y,acc[1][1]);
            acc[2][1]=fma2(a2.x,p1x,acc[2][1]); acc[2][1]=fma2(a2.y,p1y,acc[2][1]);
            acc[3][1]=fma2(a3.x,p1x,acc[3][1]); acc[3][1]=fma2(a3.y,p1y,acc[3][1]);
        }
    }
    // write partial scores
    #pragma unroll
    for (int hi = 0; hi < 4; hi++) {
        #pragma unroll
        for (int ki = 0; ki < 2; ki++) {
            float2 u = unpack2(acc[hi][ki]);
            red[s*512 + (h0+hi)*64 + kq + 32*ki] = u.x + u.y;
        }
    }
    __syncthreads();
    #pragma unroll
    for (int e0 = 0; e0 < 2; e0++) {
        int e = t + e0*256;
        float v = red[e] + red[512 + e] + red[1024 + e] + red[1536 + e];
        sc[e] = v * 0.125f;
    }
    __syncthreads();

    // ---- softmax per head ----
    if (t < 32) {
        int h = t >> 2, seg = t & 3;
        const float* p = sc + h*64 + seg*16;
        float mx = p[0];
        #pragma unroll
        for (int i = 1; i < 16; i++) mx = fmaxf(mx, p[i]);
        mx = fmaxf(mx, __shfl_xor_sync(0xffffffffu, mx, 1));
        mx = fmaxf(mx, __shfl_xor_sync(0xffffffffu, mx, 2));
        float sm = 0.f;
        #pragma unroll
        for (int i = 0; i < 16; i++) sm += __expf(p[i] - mx);
        sm += __shfl_xor_sync(0xffffffffu, sm, 1);
        sm += __shfl_xor_sync(0xffffffffu, sm, 2);
        if (seg == 0) { smax[h] = mx; srs[h] = 1.0f / sm; }
    }
    __syncthreads();
    sa[t]     = __expf(sc[t]     - smax[t >> 6])       * srs[t >> 6];
    sa[t+256] = __expf(sc[t+256] - smax[(t+256) >> 6]) * srs[(t+256) >> 6];
    __syncthreads();

    float* ctxb = g_ctx + (long)b * 4096;

    // ---- phase 3a: out cols 128..255 (skey currently holds half B) ----
    {
        int h = t >> 5, j4 = (t & 31) * 4;
        const float* sah = sa + h*64;
        u64 acc0 = 0, acc1 = 0;
        #pragma unroll 8
        for (int k = 0; k < 64; k++) {
            ull2 bv = *(const ull2*)(skey + k*SKH + j4);
            u64 av = splat2(sah[k]);
            acc0 = fma2(av, bv.x, acc0);
            acc1 = fma2(av, bv.y, acc1);
        }
        float2 u0 = unpack2(acc0), u1 = unpack2(acc1);
        *(float4*)(ctxb + h*512 + 128 + j4) = make_float4(u0.x, u0.y, u1.x, u1.y);
    }

    // ---- phase 3b: out cols 256..511 (r_proj generated, no skey) ----
    {
        int hg = t >> 6;              // 2 heads each
        int j4 = (t & 63) * 4;        // cols 256+j4
        int hA = hg*2, hB = hA+1;
        const float* saA = sa + hA*64;
        const float* saB = sa + hB*64;
        ull2 we2 = *(const ull2*)(w1e + j4);
        ull2 wo2 = *(const ull2*)(w1o + j4);
        ull2 bc2 = *(const ull2*)(b1s + j4);
        u64 aA0=0, aA1=0, aB0=0, aB1=0;
        #pragma unroll 8
        for (int k = 0; k < 64; k++) {
            u64 xs = splat2(rxy[2*k]), ys = splat2(rxy[2*k+1]);
            u64 bv0 = fma2(xs, we2.x, fma2(ys, wo2.x, bc2.x));
            u64 bv1 = fma2(xs, we2.y, fma2(ys, wo2.y, bc2.y));
            u64 vA = splat2(saA[k]), vB = splat2(saB[k]);
            aA0 = fma2(vA, bv0, aA0); aA1 = fma2(vA, bv1, aA1);
            aB0 = fma2(vB, bv0, aB0); aB1 = fma2(vB, bv1, aB1);
        }
        float2 uA0 = unpack2(aA0), uA1 = unpack2(aA1);
        float2 uB0 = unpack2(aB0), uB1 = unpack2(aB1);
        *(float4*)(ctxb + hA*512 + 256 + j4) = make_float4(uA0.x, uA0.y, uA1.x, uA1.y);
        *(float4*)(ctxb + hB*512 + 256 + j4) = make_float4(uB0.x, uB0.y, uB1.x, uB1.y);
    }

    // ---- reload skey half A, phase 3c: out cols 0..127 ----
    __syncthreads();
    #pragma unroll
    for (int q = 0; q < 8; q++) {
        int idx = t + 256*q;
        int row = idx >> 5, c4 = (idx & 31) * 4;
        *(float4*)(skey + row*SKH + c4) = *(const float4*)(keyb + row*256 + c4);
    }
    __syncthreads();
    {
        int h = t >> 5, j4 = (t & 31) * 4;
        const float* sah = sa + h*64;
        u64 acc0 = 0, acc1 = 0;
        #pragma unroll 8
        for (int k = 0; k < 64; k++) {
            ull2 bv = *(const ull2*)(skey + k*SKH + j4);
            u64 av = splat2(sah[k]);
            acc0 = fma2(av, bv.x, acc0);
            acc1 = fma2(av, bv.y, acc1);
        }
        float2 u0 = unpack2(acc0), u1 = unpack2(acc1);
        *(float4*)(ctxb + h*512 + j4) = make_float4(u0.x, u0.y, u1.x, u1.y);
    }
}

// ---------------- host launcher ----------------
extern "C" void kernel_launch(void* const* d_in, const int* in_sizes, int n_in,
                              void* d_out, int out_size) {
    const float* Z          = (const float*)d_in[0];
    const float* Q          = (const float*)d_in[1];
    const float* q_z        = (const float*)d_in[2];
    const float* r          = (const float*)d_in[3];
    const float* w1         = (const float*)d_in[4];
    const float* b1         = (const float*)d_in[5];
    const float* w2         = (const float*)d_in[6];
    const float* b2         = (const float*)d_in[7];
    const float* in_proj_w  = (const float*)d_in[8];
    const float* in_proj_b  = (const float*)d_in[9];
    const float* out_proj_w = (const float*)d_in[10];
    const float* out_proj_b = (const float*)d_in[11];
    float* outp = (float*)d_out;

    float *pCtx, *pOut1;
    cudaGetSymbolAddress((void**)&pCtx,  g_ctx);
    cudaGetSymbolAddress((void**)&pOut1, g_out1);

    cudaFuncSetAttribute(attn_kernel,
                         cudaFuncAttributeMaxDynamicSharedMemorySize, ATTN_SMEM);

    // 1) transpose Z -> Zt
    transpose_kernel<<<dim3((HWn*HWn)/32, Cn/32), dim3(32, 8)>>>(Z);

    // 2) fat: gemm1(fused query) + qz->out copy + interp
    fat_kernel<<<FAT_INTERP_OFF + NPn/32, 256>>>(
        r, q_z, Q, w2, b2, in_proj_w, in_proj_b, outp);

    // 3) qk
    qk_kernel<<<dim3(En/64, SQn/128, NHn), 256>>>(in_proj_w);

    // 4) attention v2 (occ 3)
    attn_kernel<<<SQn, 256, ATTN_SMEM>>>(r, w1, b1);

    // 5) v: out1[m][h*64+:] = ctx[m][h][:] . Wv_h + bv
    gemm_kernel<<<dim3(1, SQn/128, NHn), 256>>>(
        pCtx, NHn*En, (long)En,
        in_proj_w + (long)2*En*En, En, 1, (long)HDn*En,
        pOut1, En, (long)HDn,
        in_proj_b + (long)2*En, (long)HDn, En);

    // 6) out_proj into d_out cols [256,768)
    gemm_kernel<<<dim3(En/64, SQn/128, 1), 256>>>(
        pOut1, En, 0L,
        out_proj_w, En, 1, 0L,
        outp + 256, 768, 0L,
        out_proj_b, 0L, En);
}